// round 14
// baseline (speedup 1.0000x reference)
#include <cuda_runtime.h>

// DihedralToCartesian R14: R12 math (per-step u-normalize: rel_err ~2.5e-6;
// R13's normalize-drop rejected, margin too thin). Structural change: the 27
// per-thread points move from registers to per-warp staging smem (written as
// produced in phase 1, re-read in phase 3). Kills q[27] -> regs ~64 -> ~45,
// allowing __launch_bounds__(128, 10) => 40 warps/SM vs 32.

#define TPB    128
#define NWARP  (TPB / 32)
#define NRES   126
#define LSEG   9
#define SEGN   14
#define WSTG   1260            // per-warp floats: 504 input + 756 output
#define OUTOFF 504

__device__ __forceinline__ float frsqrt(float x) {
    float y;
    asm("rsqrt.approx.f32 %0, %1;" : "=f"(y) : "f"(x));
    return y;
}

__global__ void __launch_bounds__(TPB, 10)
dihedral_kernel(const float* __restrict__ angles,
                const float* __restrict__ prev,
                float* __restrict__ out)
{
    __shared__ __align__(16) float stg[NWARP][WSTG];

    const int lane = threadIdx.x & 31;
    const int wl   = threadIdx.x >> 5;
    const int half = lane >> 4;          // which chain of the pair
    const int s    = lane & 15;          // segment id within chain
    const bool act = (s < SEGN);

    const int chain0 = blockIdx.x * (NWARP * 2) + wl * 2;

    const float CA0 = cosf(2.028f), SA0 = sinf(2.028f), B0 = 1.329f;
    const float CA1 = cosf(2.124f), SA1 = sinf(2.124f), B1 = 1.458f;
    const float CA2 = cosf(1.941f), SA2 = sinf(1.941f), B2 = 1.523f;
    const float IS0 = 1.f / SA0, IS1 = 1.f / SA1, IS2 = 1.f / SA2;

    float* sw = stg[wl];

    // ---- phase 0: stage both chains' angle rows (504 contiguous floats) ----
    {
        const float4* src  = (const float4*)(angles + (size_t)chain0 * (2 * NRES));
        float4*       dst4 = (float4*)sw;
        #pragma unroll
        for (int r = 0; r < 4; ++r) {
            int i = lane + r * 32;
            if (i < 126) dst4[i] = src[i];
        }
    }
    __syncwarp();

    const float* msin = sw + half * 252;         // [sin 126][cos 126] per chain
    const float* mcos = msin + 126;
    const int    j0   = s * LSEG;
    float*       ob   = sw + OUTOFF + half * 378 + s * 27;   // own 27-pt slot

    // ---- phase 1: 9 serial steps; points streamed to smem (predicated) ----
    float px, py, pz, vx, vy, vz, wx, wy, wz;

    #define STEP(jj, CAk, Bk, ISk, SAk) do {                                    \
        float sn = msin[j0 + (jj)], co = mcos[j0 + (jj)];                       \
        float tt = (SAk) * frsqrt(fmaf(sn, sn, fmaf(co, co, 1e-8f)));           \
        float r1 = tt * co, r2 = -tt * sn;                                      \
        float nx = (wy * vz - wz * vy) * (ISk);                                 \
        float ny = (wz * vx - wx * vz) * (ISk);                                 \
        float nz = (wx * vy - wy * vx) * (ISk);                                 \
        float mx = wy * nz - wz * ny;                                           \
        float my = wz * nx - wx * nz;                                           \
        float mz = wx * ny - wy * nx;                                           \
        float ux = fmaf(-(CAk), wx, fmaf(r1, mx, r2 * nx));                     \
        float uy = fmaf(-(CAk), wy, fmaf(r1, my, r2 * ny));                     \
        float uz = fmaf(-(CAk), wz, fmaf(r1, mz, r2 * nz));                     \
        px = fmaf((Bk), ux, px);                                                \
        py = fmaf((Bk), uy, py);                                                \
        pz = fmaf((Bk), uz, pz);                                                \
        if (act) {                                                              \
            ob[(jj) * 3 + 0] = px;                                              \
            ob[(jj) * 3 + 1] = py;                                              \
            ob[(jj) * 3 + 2] = pz;                                              \
        }                                                                       \
        float iun = frsqrt(fmaf(ux, ux, fmaf(uy, uy, uz * uz)));                \
        vx = wx; vy = wy; vz = wz;                                              \
        wx = ux * iun; wy = uy * iun; wz = uz * iun;                            \
    } while (0)

    if (s == 0) {
        // real geometry from prev_three; reference-faithful first step
        const float* pp = prev + (size_t)(chain0 + half) * 9;
        float ax = pp[0], ay = pp[1], az = pp[2];
        float bx = pp[3], by = pp[4], bz = pp[5];
        px = pp[6]; py = pp[7]; pz = pp[8];

        float sn = msin[0], co = mcos[0];
        float tt = SA0 * frsqrt(fmaf(sn, sn, fmaf(co, co, 1e-8f)));
        float r1 = tt * co, r2 = -tt * sn;

        float bcx = (bx - px) + 1e-8f;
        float bcy = (by - py) + 1e-8f;
        float bcz = (bz - pz) + 1e-8f;
        float ib = frsqrt(fmaf(bcx, bcx, fmaf(bcy, bcy, bcz * bcz)));
        bcx *= ib; bcy *= ib; bcz *= ib;

        float qx = bx - ax, qy = by - ay, qz = bz - az;
        float nx = fmaf(qy, bcz, fmaf(-qz, bcy, 1e-8f));
        float ny = fmaf(qz, bcx, fmaf(-qx, bcz, 1e-8f));
        float nz = fmaf(qx, bcy, fmaf(-qy, bcx, 1e-8f));
        float in_ = frsqrt(fmaf(nx, nx, fmaf(ny, ny, nz * nz)));
        nx *= in_; ny *= in_; nz *= in_;

        float mx = ny * bcz - nz * bcy;
        float my = nz * bcx - nx * bcz;
        float mz = nx * bcy - ny * bcx;

        float ux = fmaf(CA0, bcx, fmaf(r1, mx, r2 * nx));
        float uy = fmaf(CA0, bcy, fmaf(r1, my, r2 * ny));
        float uz = fmaf(CA0, bcz, fmaf(r1, mz, r2 * nz));

        px = fmaf(B0, ux, px);
        py = fmaf(B0, uy, py);
        pz = fmaf(B0, uz, pz);
        ob[0] = px; ob[1] = py; ob[2] = pz;

        float iun = frsqrt(fmaf(ux, ux, fmaf(uy, uy, uz * uz)));
        vx = -bcx; vy = -bcy; vz = -bcz;
        wx = ux * iun; wy = uy * iun; wz = uz * iun;
    } else {
        // canonical entry frame (segment boundary geometry is constant)
        px = 0.f; py = 0.f; pz = 0.f;
        wx = 1.f; wy = 0.f; wz = 0.f;
        vx = -CA2; vy = SA2; vz = 0.f;
        STEP(0, CA0, B0, IS2, SA0);
    }
    STEP(1, CA1, B1, IS0, SA1);
    STEP(2, CA2, B2, IS1, SA2);
    STEP(3, CA0, B0, IS2, SA0);
    STEP(4, CA1, B1, IS0, SA1);
    STEP(5, CA2, B2, IS1, SA2);
    STEP(6, CA0, B0, IS2, SA0);
    STEP(7, CA1, B1, IS0, SA1);
    STEP(8, CA2, B2, IS1, SA2);
    #undef STEP

    // ---- phase 2: local rigid map L_s = (GS(w, v) | p) ----
    float c1x = wx, c1y = wy, c1z = wz;
    float dvw = fmaf(vx, wx, fmaf(vy, wy, vz * wz));
    float tx = fmaf(-dvw, wx, vx);
    float ty = fmaf(-dvw, wy, vy);
    float tz = fmaf(-dvw, wz, vz);
    float it = frsqrt(fmaf(tx, tx, fmaf(ty, ty, fmaf(tz, tz, 1e-20f))));
    float c2x = tx * it, c2y = ty * it, c2z = tz * it;
    float c3x = c1y * c2z - c1z * c2y;
    float c3y = c1z * c2x - c1x * c2z;
    float c3z = c1x * c2y - c1y * c2x;
    float cpx = px, cpy = py, cpz = pz;

    // ---- inclusive Hillis-Steele scan over rigid maps (width 16) ----
    #pragma unroll
    for (int d = 1; d < 16; d <<= 1) {          // 1, 2, 4, 8
        float L1x = __shfl_up_sync(0xffffffffu, c1x, d, 16);
        float L1y = __shfl_up_sync(0xffffffffu, c1y, d, 16);
        float L1z = __shfl_up_sync(0xffffffffu, c1z, d, 16);
        float L2x = __shfl_up_sync(0xffffffffu, c2x, d, 16);
        float L2y = __shfl_up_sync(0xffffffffu, c2y, d, 16);
        float L2z = __shfl_up_sync(0xffffffffu, c2z, d, 16);
        float L3x = __shfl_up_sync(0xffffffffu, c3x, d, 16);
        float L3y = __shfl_up_sync(0xffffffffu, c3y, d, 16);
        float L3z = __shfl_up_sync(0xffffffffu, c3z, d, 16);
        float Lpx = __shfl_up_sync(0xffffffffu, cpx, d, 16);
        float Lpy = __shfl_up_sync(0xffffffffu, cpy, d, 16);
        float Lpz = __shfl_up_sync(0xffffffffu, cpz, d, 16);
        if (s >= d) {
            float n1x = fmaf(c1x, L1x, fmaf(c1y, L2x, c1z * L3x));
            float n1y = fmaf(c1x, L1y, fmaf(c1y, L2y, c1z * L3y));
            float n1z = fmaf(c1x, L1z, fmaf(c1y, L2z, c1z * L3z));
            float n2x = fmaf(c2x, L1x, fmaf(c2y, L2x, c2z * L3x));
            float n2y = fmaf(c2x, L1y, fmaf(c2y, L2y, c2z * L3y));
            float n2z = fmaf(c2x, L1z, fmaf(c2y, L2z, c2z * L3z));
            float n3x = fmaf(c3x, L1x, fmaf(c3y, L2x, c3z * L3x));
            float n3y = fmaf(c3x, L1y, fmaf(c3y, L2y, c3z * L3y));
            float n3z = fmaf(c3x, L1z, fmaf(c3y, L2z, c3z * L3z));
            float npx = fmaf(cpx, L1x, fmaf(cpy, L2x, fmaf(cpz, L3x, Lpx)));
            float npy = fmaf(cpx, L1y, fmaf(cpy, L2y, fmaf(cpz, L3y, Lpy)));
            float npz = fmaf(cpx, L1z, fmaf(cpy, L2z, fmaf(cpz, L3z, Lpz)));
            c1x = n1x; c1y = n1y; c1z = n1z;
            c2x = n2x; c2y = n2y; c2z = n2z;
            c3x = n3x; c3y = n3y; c3z = n3z;
            cpx = npx; cpy = npy; cpz = npz;
        }
    }

    // ---- exclusive prefix: T_s = P_{s-1}; identity at s == 0 ----
    float t1x = __shfl_up_sync(0xffffffffu, c1x, 1, 16);
    float t1y = __shfl_up_sync(0xffffffffu, c1y, 1, 16);
    float t1z = __shfl_up_sync(0xffffffffu, c1z, 1, 16);
    float t2x = __shfl_up_sync(0xffffffffu, c2x, 1, 16);
    float t2y = __shfl_up_sync(0xffffffffu, c2y, 1, 16);
    float t2z = __shfl_up_sync(0xffffffffu, c2z, 1, 16);
    float t3x = __shfl_up_sync(0xffffffffu, c3x, 1, 16);
    float t3y = __shfl_up_sync(0xffffffffu, c3y, 1, 16);
    float t3z = __shfl_up_sync(0xffffffffu, c3z, 1, 16);
    float tpx = __shfl_up_sync(0xffffffffu, cpx, 1, 16);
    float tpy = __shfl_up_sync(0xffffffffu, cpy, 1, 16);
    float tpz = __shfl_up_sync(0xffffffffu, cpz, 1, 16);
    if (s == 0) {
        t1x = 1.f; t1y = 0.f; t1z = 0.f;
        t2x = 0.f; t2y = 1.f; t2z = 0.f;
        t3x = 0.f; t3y = 0.f; t3z = 1.f;
        tpx = 0.f; tpy = 0.f; tpz = 0.f;
    }

    // ---- phase 3: transform own 9 points in smem (read, rotate, write) ----
    __syncwarp();
    if (act) {
        #pragma unroll
        for (int jj = 0; jj < LSEG; ++jj) {
            float qx = ob[jj * 3 + 0];
            float qy = ob[jj * 3 + 1];
            float qz = ob[jj * 3 + 2];
            ob[jj * 3 + 0] = fmaf(qx, t1x, fmaf(qy, t2x, fmaf(qz, t3x, tpx)));
            ob[jj * 3 + 1] = fmaf(qx, t1y, fmaf(qy, t2y, fmaf(qz, t3y, tpy)));
            ob[jj * 3 + 2] = fmaf(qx, t1z, fmaf(qy, t2z, fmaf(qz, t3z, tpz)));
        }
    }
    __syncwarp();

    // ---- phase 4: coalesced float4 flush (756 floats = 189 float4) ----
    {
        float4*       dst  = (float4*)(out + (size_t)chain0 * (NRES * 3));
        const float4* src4 = (const float4*)(sw + OUTOFF);
        #pragma unroll
        for (int r = 0; r < 6; ++r) {
            int i = lane + r * 32;
            if (i < 189) dst[i] = src4[i];
        }
    }
}

extern "C" void kernel_launch(void* const* d_in, const int* in_sizes, int n_in,
                              void* d_out, int out_size)
{
    const float* angles = (const float*)d_in[0];   // (B, 252) f32
    const float* prev   = (const float*)d_in[1];   // (B, 3, 3) f32
    float*       out    = (float*)d_out;           // (B, 126, 3) f32

    const int B = in_sizes[0] / (2 * NRES);        // 65536
    dihedral_kernel<<<B / (NWARP * 2), TPB>>>(angles, prev, out);
}

// round 15
// speedup vs baseline: 1.1535x; 1.1535x over previous
#include <cuda_runtime.h>

// DihedralToCartesian R15: R12 structure (champion) with the phase-1 step
// reformulated on an orthonormal (w, n) carry:
//   m = w x n;  h = cn*m - sm*n;  u' = -CA*w + SA*h  (|u'| = 1 exactly)
//   n' = cn*n + sm*m              (plane rotation; no cross, no 1/sin)
// No per-step normalize; one renorm+reorthogonalization mid-segment bounds
// drift at ~2e-6 (error-growth model validated against R13's measurement).
// Segment exit basis is exactly (w, n x w, n) -> Gram-Schmidt replaced by
// one ortho-correction + one cross.

#define TPB    128
#define NWARP  (TPB / 32)
#define NRES   126
#define LSEG   9
#define SEGN   14

__device__ __forceinline__ float frsqrt(float x) {
    float y;
    asm("rsqrt.approx.f32 %0, %1;" : "=f"(y) : "f"(x));
    return y;
}

__global__ void __launch_bounds__(TPB, 8)
dihedral_kernel(const float* __restrict__ angles,
                const float* __restrict__ prev,
                float* __restrict__ out)
{
    // per-warp staging: 756 floats (input uses first 504; output uses all 756)
    __shared__ __align__(16) float stg[NWARP][756];

    const int lane = threadIdx.x & 31;
    const int wl   = threadIdx.x >> 5;
    const int half = lane >> 4;          // which chain of the pair
    const int s    = lane & 15;          // segment id within chain
    const bool act = (s < SEGN);

    const int chain0 = blockIdx.x * (NWARP * 2) + wl * 2;

    const float CA0 = cosf(2.028f), SA0 = sinf(2.028f), B0 = 1.329f;
    const float CA1 = cosf(2.124f), SA1 = sinf(2.124f), B1 = 1.458f;
    const float CA2 = cosf(1.941f), SA2 = sinf(1.941f), B2 = 1.523f;

    float* sw = stg[wl];

    // ---- phase 0: stage both chains' angle rows (504 contiguous floats) ----
    {
        const float4* src  = (const float4*)(angles + (size_t)chain0 * (2 * NRES));
        float4*       dst4 = (float4*)sw;
        #pragma unroll
        for (int r = 0; r < 4; ++r) {
            int i = lane + r * 32;
            if (i < 126) dst4[i] = src[i];
        }
    }
    __syncwarp();

    const float* msin = sw + half * 252;         // [sin 126][cos 126] per chain
    const float* mcos = msin + 126;
    const int    j0   = s * LSEG;

    // ---- phase 1: 9 serial steps on orthonormal (w, n) carry ----
    float px, py, pz, wx, wy, wz, nx, ny, nz;
    float q[LSEG * 3];

    #define STEP(jj, CAk, Bk, SAk) do {                                         \
        float sn = msin[j0 + (jj)], co = mcos[j0 + (jj)];                       \
        float inv = frsqrt(fmaf(sn, sn, fmaf(co, co, 1e-8f)));                  \
        float cn = co * inv, sm = sn * inv;                                     \
        float mx = wy * nz - wz * ny;                                           \
        float my = wz * nx - wx * nz;                                           \
        float mz = wx * ny - wy * nx;                                           \
        float hx = fmaf(cn, mx, -sm * nx);                                      \
        float hy = fmaf(cn, my, -sm * ny);                                      \
        float hz = fmaf(cn, mz, -sm * nz);                                      \
        float ux = fmaf(-(CAk), wx, (SAk) * hx);                                \
        float uy = fmaf(-(CAk), wy, (SAk) * hy);                                \
        float uz = fmaf(-(CAk), wz, (SAk) * hz);                                \
        px = fmaf((Bk), ux, px);                                                \
        py = fmaf((Bk), uy, py);                                                \
        pz = fmaf((Bk), uz, pz);                                                \
        q[(jj) * 3 + 0] = px; q[(jj) * 3 + 1] = py; q[(jj) * 3 + 2] = pz;       \
        float n2x = fmaf(cn, nx, sm * mx);                                      \
        float n2y = fmaf(cn, ny, sm * my);                                      \
        float n2z = fmaf(cn, nz, sm * mz);                                      \
        nx = n2x; ny = n2y; nz = n2z;                                           \
        wx = ux; wy = uy; wz = uz;                                              \
    } while (0)

    if (s == 0) {
        // real geometry from prev_three; reference-faithful first step
        const float* pp = prev + (size_t)(chain0 + half) * 9;
        float ax = pp[0], ay = pp[1], az = pp[2];
        float bx = pp[3], by = pp[4], bz = pp[5];
        px = pp[6]; py = pp[7]; pz = pp[8];

        float sn = msin[0], co = mcos[0];
        float inv = frsqrt(fmaf(sn, sn, fmaf(co, co, 1e-8f)));
        float cn = co * inv, sm = sn * inv;
        float r1 = SA0 * cn, r2 = -SA0 * sm;

        float bcx = (bx - px) + 1e-8f;
        float bcy = (by - py) + 1e-8f;
        float bcz = (bz - pz) + 1e-8f;
        float ib = frsqrt(fmaf(bcx, bcx, fmaf(bcy, bcy, bcz * bcz)));
        bcx *= ib; bcy *= ib; bcz *= ib;

        float qx = bx - ax, qy = by - ay, qz = bz - az;
        float Nx = fmaf(qy, bcz, fmaf(-qz, bcy, 1e-8f));
        float Ny = fmaf(qz, bcx, fmaf(-qx, bcz, 1e-8f));
        float Nz = fmaf(qx, bcy, fmaf(-qy, bcx, 1e-8f));
        float iN = frsqrt(fmaf(Nx, Nx, fmaf(Ny, Ny, Nz * Nz)));
        Nx *= iN; Ny *= iN; Nz *= iN;

        float mx = Ny * bcz - Nz * bcy;     // m = N x bc (== w_old x N)
        float my = Nz * bcx - Nx * bcz;
        float mz = Nx * bcy - Ny * bcx;

        float ux = fmaf(CA0, bcx, fmaf(r1, mx, r2 * Nx));
        float uy = fmaf(CA0, bcy, fmaf(r1, my, r2 * Ny));
        float uz = fmaf(CA0, bcz, fmaf(r1, mz, r2 * Nz));

        px = fmaf(B0, ux, px);
        py = fmaf(B0, uy, py);
        pz = fmaf(B0, uz, pz);
        q[0] = px; q[1] = py; q[2] = pz;

        wx = ux; wy = uy; wz = uz;           // |u| = 1 + O(eps)
        nx = fmaf(cn, Nx, sm * mx);          // n' = cn*N + sm*m
        ny = fmaf(cn, Ny, sm * my);
        nz = fmaf(cn, Nz, sm * mz);
    } else {
        // canonical entry frame: w0 = e1, n0 = e3 (constant boundary geometry)
        px = 0.f; py = 0.f; pz = 0.f;
        wx = 1.f; wy = 0.f; wz = 0.f;
        nx = 0.f; ny = 0.f; nz = 1.f;
        STEP(0, CA0, B0, SA0);
    }
    STEP(1, CA1, B1, SA1);
    STEP(2, CA2, B2, SA2);
    STEP(3, CA0, B0, SA0);
    STEP(4, CA1, B1, SA1);

    // mid-segment drift correction: renormalize w; reorthogonalize+renorm n
    {
        float iw = frsqrt(fmaf(wx, wx, fmaf(wy, wy, wz * wz)));
        wx *= iw; wy *= iw; wz *= iw;
        float d = fmaf(nx, wx, fmaf(ny, wy, nz * wz));
        nx = fmaf(-d, wx, nx);
        ny = fmaf(-d, wy, ny);
        nz = fmaf(-d, wz, nz);
        float in_ = frsqrt(fmaf(nx, nx, fmaf(ny, ny, nz * nz)));
        nx *= in_; ny *= in_; nz *= in_;
    }

    STEP(5, CA2, B2, SA2);
    STEP(6, CA0, B0, SA0);
    STEP(7, CA1, B1, SA1);
    STEP(8, CA2, B2, SA2);
    #undef STEP

    // ---- phase 2: exit basis (g1, g2, g3) = (w, n x w, n), orthonormalized --
    float c1x, c1y, c1z, c2x, c2y, c2z, c3x, c3y, c3z;
    {
        float iw = frsqrt(fmaf(wx, wx, fmaf(wy, wy, wz * wz)));
        c1x = wx * iw; c1y = wy * iw; c1z = wz * iw;
        float d = fmaf(nx, c1x, fmaf(ny, c1y, nz * c1z));
        float tx = fmaf(-d, c1x, nx);
        float ty = fmaf(-d, c1y, ny);
        float tz = fmaf(-d, c1z, nz);
        float it = frsqrt(fmaf(tx, tx, fmaf(ty, ty, fmaf(tz, tz, 1e-20f))));
        c3x = tx * it; c3y = ty * it; c3z = tz * it;
        c2x = c3y * c1z - c3z * c1y;         // g2 = g3 x g1
        c2y = c3z * c1x - c3x * c1z;
        c2z = c3x * c1y - c3y * c1x;
    }
    float cpx = px, cpy = py, cpz = pz;

    // ---- inclusive Hillis-Steele scan over rigid maps (width 16) ----
    #pragma unroll
    for (int d = 1; d < 16; d <<= 1) {          // 1, 2, 4, 8
        float L1x = __shfl_up_sync(0xffffffffu, c1x, d, 16);
        float L1y = __shfl_up_sync(0xffffffffu, c1y, d, 16);
        float L1z = __shfl_up_sync(0xffffffffu, c1z, d, 16);
        float L2x = __shfl_up_sync(0xffffffffu, c2x, d, 16);
        float L2y = __shfl_up_sync(0xffffffffu, c2y, d, 16);
        float L2z = __shfl_up_sync(0xffffffffu, c2z, d, 16);
        float L3x = __shfl_up_sync(0xffffffffu, c3x, d, 16);
        float L3y = __shfl_up_sync(0xffffffffu, c3y, d, 16);
        float L3z = __shfl_up_sync(0xffffffffu, c3z, d, 16);
        float Lpx = __shfl_up_sync(0xffffffffu, cpx, d, 16);
        float Lpy = __shfl_up_sync(0xffffffffu, cpy, d, 16);
        float Lpz = __shfl_up_sync(0xffffffffu, cpz, d, 16);
        if (s >= d) {
            float n1x = fmaf(c1x, L1x, fmaf(c1y, L2x, c1z * L3x));
            float n1y = fmaf(c1x, L1y, fmaf(c1y, L2y, c1z * L3y));
            float n1z = fmaf(c1x, L1z, fmaf(c1y, L2z, c1z * L3z));
            float n2x = fmaf(c2x, L1x, fmaf(c2y, L2x, c2z * L3x));
            float n2y = fmaf(c2x, L1y, fmaf(c2y, L2y, c2z * L3y));
            float n2z = fmaf(c2x, L1z, fmaf(c2y, L2z, c2z * L3z));
            float n3x = fmaf(c3x, L1x, fmaf(c3y, L2x, c3z * L3x));
            float n3y = fmaf(c3x, L1y, fmaf(c3y, L2y, c3z * L3y));
            float n3z = fmaf(c3x, L1z, fmaf(c3y, L2z, c3z * L3z));
            float npx = fmaf(cpx, L1x, fmaf(cpy, L2x, fmaf(cpz, L3x, Lpx)));
            float npy = fmaf(cpx, L1y, fmaf(cpy, L2y, fmaf(cpz, L3y, Lpy)));
            float npz = fmaf(cpx, L1z, fmaf(cpy, L2z, fmaf(cpz, L3z, Lpz)));
            c1x = n1x; c1y = n1y; c1z = n1z;
            c2x = n2x; c2y = n2y; c2z = n2z;
            c3x = n3x; c3y = n3y; c3z = n3z;
            cpx = npx; cpy = npy; cpz = npz;
        }
    }

    // ---- exclusive prefix: T_s = P_{s-1}; identity at s == 0 ----
    float t1x = __shfl_up_sync(0xffffffffu, c1x, 1, 16);
    float t1y = __shfl_up_sync(0xffffffffu, c1y, 1, 16);
    float t1z = __shfl_up_sync(0xffffffffu, c1z, 1, 16);
    float t2x = __shfl_up_sync(0xffffffffu, c2x, 1, 16);
    float t2y = __shfl_up_sync(0xffffffffu, c2y, 1, 16);
    float t2z = __shfl_up_sync(0xffffffffu, c2z, 1, 16);
    float t3x = __shfl_up_sync(0xffffffffu, c3x, 1, 16);
    float t3y = __shfl_up_sync(0xffffffffu, c3y, 1, 16);
    float t3z = __shfl_up_sync(0xffffffffu, c3z, 1, 16);
    float tpx = __shfl_up_sync(0xffffffffu, cpx, 1, 16);
    float tpy = __shfl_up_sync(0xffffffffu, cpy, 1, 16);
    float tpz = __shfl_up_sync(0xffffffffu, cpz, 1, 16);
    if (s == 0) {
        t1x = 1.f; t1y = 0.f; t1z = 0.f;
        t2x = 0.f; t2y = 1.f; t2z = 0.f;
        t3x = 0.f; t3y = 0.f; t3z = 1.f;
        tpx = 0.f; tpy = 0.f; tpz = 0.f;
    }

    // ---- phase 3: transform own 9 points, stage to smem (input dead now) ----
    __syncwarp();
    if (act) {
        float* ob = sw + half * 378 + s * 27;
        #pragma unroll
        for (int jj = 0; jj < LSEG; ++jj) {
            float qx = q[jj * 3 + 0];
            float qy = q[jj * 3 + 1];
            float qz = q[jj * 3 + 2];
            ob[jj * 3 + 0] = fmaf(qx, t1x, fmaf(qy, t2x, fmaf(qz, t3x, tpx)));
            ob[jj * 3 + 1] = fmaf(qx, t1y, fmaf(qy, t2y, fmaf(qz, t3y, tpy)));
            ob[jj * 3 + 2] = fmaf(qx, t1z, fmaf(qy, t2z, fmaf(qz, t3z, tpz)));
        }
    }
    __syncwarp();

    // ---- phase 4: coalesced float4 flush (756 floats = 189 float4) ----
    {
        float4*       dst  = (float4*)(out + (size_t)chain0 * (NRES * 3));
        const float4* src4 = (const float4*)sw;
        #pragma unroll
        for (int r = 0; r < 6; ++r) {
            int i = lane + r * 32;
            if (i < 189) dst[i] = src4[i];
        }
    }
}

extern "C" void kernel_launch(void* const* d_in, const int* in_sizes, int n_in,
                              void* d_out, int out_size)
{
    const float* angles = (const float*)d_in[0];   // (B, 252) f32
    const float* prev   = (const float*)d_in[1];   // (B, 3, 3) f32
    float*       out    = (float*)d_out;           // (B, 126, 3) f32

    const int B = in_sizes[0] / (2 * NRES);        // 65536
    dihedral_kernel<<<B / (NWARP * 2), TPB>>>(angles, prev, out);
}